// round 2
// baseline (speedup 1.0000x reference)
#include <cuda_runtime.h>

#define NN 100000   // nodes
#define NE 1600000  // edges
#define NF 128      // input features
#define NH 64       // hidden
#define NC 10       // classes
#define NL 3        // layers
#define NG 1000     // graphs

// Scratch (device globals: no allocation allowed in kernel_launch)
__device__ float g_h[NN * NH];
__device__ float g_agg[NN * NH];
__device__ float g_t[NN * NH];
__device__ float g_pool[NG * NH];
__device__ float g_g2[NG * NH];

// ---------------------------------------------------------------------------
// zero: float4 grid-stride
// ---------------------------------------------------------------------------
__global__ void zero_kernel(float* __restrict__ p, int n4) {
    float4 z = make_float4(0.f, 0.f, 0.f, 0.f);
    for (int i = blockIdx.x * blockDim.x + threadIdx.x; i < n4;
         i += gridDim.x * blockDim.x)
        reinterpret_cast<float4*>(p)[i] = z;
}

// ---------------------------------------------------------------------------
// GEMM: out[N,64] = act(  (A [+ A2]) [N,K] @ W [K,64] + b )
// Block = 256 threads, processes ROWS rows. W resident in smem.
// ---------------------------------------------------------------------------
template <int K, int ROWS, bool RELU, bool ADD2>
__global__ void gemm_kernel(const float* __restrict__ A,
                            const float* __restrict__ A2,
                            const float* __restrict__ W,
                            const float* __restrict__ bias,
                            float* __restrict__ out, int N) {
    constexpr int TPR = 256 / ROWS;  // threads per row
    constexpr int CPT = 64 / TPR;    // cols per thread
    constexpr int STR = K + 1;       // As row stride (bank-conflict pad)

    __shared__ float Ws[K * 64];
    __shared__ float As[ROWS * STR];

    const int tid  = threadIdx.x;
    const int row0 = blockIdx.x * ROWS;

    // Stage W (coalesced)
    for (int i = tid; i < K * 64; i += 256) Ws[i] = W[i];

    // Stage A tile (coalesced), fold in A2 (= h + agg) if requested
    for (int i = tid; i < ROWS * K; i += 256) {
        int r = i / K, k = i - r * K;
        int gr = row0 + r;
        float v = 0.f;
        if (gr < N) {
            size_t gi = (size_t)gr * K + k;
            v = A[gi];
            if (ADD2) v += A2[gi];
        }
        As[r * STR + k] = v;
    }
    __syncthreads();

    const int row = tid / TPR;
    const int cb  = (tid % TPR) * CPT;

    float acc[CPT];
    #pragma unroll
    for (int j = 0; j < CPT; j++) acc[j] = 0.f;

    #pragma unroll 8
    for (int k = 0; k < K; k++) {
        float a = As[row * STR + k];
        const float4* w4 = reinterpret_cast<const float4*>(Ws + k * 64 + cb);
        #pragma unroll
        for (int j4 = 0; j4 < CPT / 4; j4++) {
            float4 w = w4[j4];
            acc[j4 * 4 + 0] = fmaf(a, w.x, acc[j4 * 4 + 0]);
            acc[j4 * 4 + 1] = fmaf(a, w.y, acc[j4 * 4 + 1]);
            acc[j4 * 4 + 2] = fmaf(a, w.z, acc[j4 * 4 + 2]);
            acc[j4 * 4 + 3] = fmaf(a, w.w, acc[j4 * 4 + 3]);
        }
    }

    const int gr = row0 + row;
    if (gr < N) {
        #pragma unroll
        for (int j4 = 0; j4 < CPT / 4; j4++) {
            float4 v;
            v.x = acc[j4 * 4 + 0] + bias[cb + j4 * 4 + 0];
            v.y = acc[j4 * 4 + 1] + bias[cb + j4 * 4 + 1];
            v.z = acc[j4 * 4 + 2] + bias[cb + j4 * 4 + 2];
            v.w = acc[j4 * 4 + 3] + bias[cb + j4 * 4 + 3];
            if (RELU) {
                v.x = fmaxf(v.x, 0.f); v.y = fmaxf(v.y, 0.f);
                v.z = fmaxf(v.z, 0.f); v.w = fmaxf(v.w, 0.f);
            }
            reinterpret_cast<float4*>(out + (size_t)gr * 64 + cb)[j4] = v;
        }
    }
}

// ---------------------------------------------------------------------------
// Edge scatter: agg[dst] += h[src].  One warp per edge, float2 per lane.
// Indices are int32 (JAX default x64-disabled downcasts int64 -> int32).
// ---------------------------------------------------------------------------
__global__ void scatter_kernel(const float* __restrict__ h,
                               const int* __restrict__ ei,
                               float* __restrict__ agg) {
    int e = blockIdx.x * 8 + (threadIdx.x >> 5);
    if (e >= NE) return;
    int lane = threadIdx.x & 31;
    int s = __ldg(ei + e);        // src
    int d = __ldg(ei + NE + e);   // dst
    if ((unsigned)s >= NN || (unsigned)d >= NN) return;  // defensive
    float2 v = reinterpret_cast<const float2*>(h + (size_t)s * NH)[lane];
    float* ap = agg + (size_t)d * NH + lane * 2;
    atomicAdd(ap, v.x);
    atomicAdd(ap + 1, v.y);
}

// ---------------------------------------------------------------------------
// Global add pool: pool[batch[n]] += h[n].  One warp per node.
// ---------------------------------------------------------------------------
__global__ void pool_kernel(const float* __restrict__ h,
                            const int* __restrict__ batch,
                            float* __restrict__ pool) {
    int n = blockIdx.x * 8 + (threadIdx.x >> 5);
    if (n >= NN) return;
    int lane = threadIdx.x & 31;
    int g = __ldg(batch + n);
    if ((unsigned)g >= NG) return;  // defensive
    float2 v = reinterpret_cast<const float2*>(h + (size_t)n * NH)[lane];
    float* pp = pool + (size_t)g * NH + lane * 2;
    atomicAdd(pp, v.x);
    atomicAdd(pp + 1, v.y);
}

// ---------------------------------------------------------------------------
// Readout: logits = g2 @ roW + rob; out = log_softmax(logits).
// One warp per graph row; lanes 0..9 own classes.
// ---------------------------------------------------------------------------
__global__ void readout_kernel(const float* __restrict__ g2,
                               const float* __restrict__ roW,
                               const float* __restrict__ rob,
                               float* __restrict__ out) {
    int row = blockIdx.x * 8 + (threadIdx.x >> 5);
    if (row >= NG) return;
    int lane = threadIdx.x & 31;

    float acc = 0.f;
    if (lane < NC) {
        acc = rob[lane];
        #pragma unroll
        for (int k = 0; k < NH; k++)
            acc = fmaf(g2[(size_t)row * NH + k], roW[k * NC + lane], acc);
    }
    // warp max over valid lanes
    float m = (lane < NC) ? acc : -3.4e38f;
    #pragma unroll
    for (int o = 16; o > 0; o >>= 1)
        m = fmaxf(m, __shfl_xor_sync(0xffffffffu, m, o));
    float e = (lane < NC) ? expf(acc - m) : 0.f;
    float s = e;
    #pragma unroll
    for (int o = 16; o > 0; o >>= 1)
        s += __shfl_xor_sync(0xffffffffu, s, o);
    if (lane < NC) out[(size_t)row * NC + lane] = acc - m - logf(s);
}

// ---------------------------------------------------------------------------
extern "C" void kernel_launch(void* const* d_in, const int* in_sizes, int n_in,
                              void* d_out, int out_size) {
    const float* x      = (const float*)d_in[0];
    const int*   ei     = (const int*)d_in[1];
    const int*   batch  = (const int*)d_in[2];
    const float* pre_w  = (const float*)d_in[3];
    const float* pre_b  = (const float*)d_in[4];
    const float* w1     = (const float*)d_in[5];   // [3,64,64]
    const float* b1     = (const float*)d_in[6];   // [3,64]
    const float* w2     = (const float*)d_in[7];
    const float* b2     = (const float*)d_in[8];
    const float* post_w = (const float*)d_in[9];
    const float* post_b = (const float*)d_in[10];
    const float* ro_w   = (const float*)d_in[11];
    const float* ro_b   = (const float*)d_in[12];
    float*       out    = (float*)d_out;

    float *hP, *aggP, *tP, *poolP, *g2P;
    cudaGetSymbolAddress((void**)&hP,    g_h);
    cudaGetSymbolAddress((void**)&aggP,  g_agg);
    cudaGetSymbolAddress((void**)&tP,    g_t);
    cudaGetSymbolAddress((void**)&poolP, g_pool);
    cudaGetSymbolAddress((void**)&g2P,   g_g2);

    // h = x @ pre_w + pre_b
    gemm_kernel<128, 16, false, false><<<(NN + 15) / 16, 256>>>(
        x, nullptr, pre_w, pre_b, hP, NN);

    for (int l = 0; l < NL; l++) {
        zero_kernel<<<2048, 256>>>(aggP, NN * NH / 4);
        scatter_kernel<<<(NE + 7) / 8, 256>>>(hP, ei, aggP);
        // t = relu((h + agg) @ w1 + b1)
        gemm_kernel<64, 64, true, true><<<(NN + 63) / 64, 256>>>(
            hP, aggP, w1 + l * NH * NH, b1 + l * NH, tP, NN);
        // h = relu(t @ w2 + b2)
        gemm_kernel<64, 64, true, false><<<(NN + 63) / 64, 256>>>(
            tP, nullptr, w2 + l * NH * NH, b2 + l * NH, hP, NN);
    }

    zero_kernel<<<64, 256>>>(poolP, NG * NH / 4);
    pool_kernel<<<(NN + 7) / 8, 256>>>(hP, batch, poolP);
    // g2 = relu(pool @ post_w + post_b)
    gemm_kernel<64, 64, true, false><<<(NG + 63) / 64, 256>>>(
        poolP, nullptr, post_w, post_b, g2P, NG);
    readout_kernel<<<(NG + 7) / 8, 256>>>(g2P, ro_w, ro_b, out);
}

// round 3
// speedup vs baseline: 1.9938x; 1.9938x over previous
#include <cuda_runtime.h>

#define NN 100000   // nodes
#define NE 1600000  // edges
#define NF 128      // input features
#define NH 64       // hidden
#define NC 10       // classes
#define NL 3        // layers
#define NG 1000     // graphs

// Scratch (device globals: no allocation allowed in kernel_launch)
__device__ float g_h[NN * NH];
__device__ float g_agg[NN * NH];
__device__ float g_t[NN * NH];
__device__ float g_pool[NG * NH];
__device__ float g_g2[NG * NH];

// ---------------------------------------------------------------------------
// zero: float4 grid-stride
// ---------------------------------------------------------------------------
__global__ void zero_kernel(float* __restrict__ p, int n4) {
    float4 z = make_float4(0.f, 0.f, 0.f, 0.f);
    for (int i = blockIdx.x * blockDim.x + threadIdx.x; i < n4;
         i += gridDim.x * blockDim.x)
        reinterpret_cast<float4*>(p)[i] = z;
}

// ---------------------------------------------------------------------------
// GEMM: out[N,64] = act( (A [+ A2]) [N,K] @ W [K,64] + b )
// Block 256 threads, 128 rows/block. Register tile: 4 rows x 8 cols / thread.
// Per k: 4 A-LDS (conflict-free) + 2 W-LDS.128 for 32 FFMA  -> FMA-bound.
// ---------------------------------------------------------------------------
template <int K, bool RELU, bool ADD2>
__global__ __launch_bounds__(256)
void gemm_kernel(const float* __restrict__ A,
                 const float* __restrict__ A2,
                 const float* __restrict__ W,
                 const float* __restrict__ bias,
                 float* __restrict__ out, int N) {
    constexpr int ROWS = 128;
    constexpr int STR  = K + 1;  // bank-conflict pad (row banks distinct mod 32)

    extern __shared__ float sm[];
    float* Ws = sm;            // K * 64
    float* As = sm + K * 64;   // ROWS * STR

    const int tid  = threadIdx.x;
    const int row0 = blockIdx.x * ROWS;

    // Stage W (coalesced)
    for (int i = tid; i < K * 64; i += 256) Ws[i] = W[i];

    // Stage A tile (coalesced), fold in A2 (= h + agg) if requested
    for (int i = tid; i < ROWS * K; i += 256) {
        int r = i / K, k = i - r * K;
        int gr = row0 + r;
        float v = 0.f;
        if (gr < N) {
            size_t gi = (size_t)gr * K + k;
            v = A[gi];
            if (ADD2) v += A2[gi];
        }
        As[r * STR + k] = v;
    }
    __syncthreads();

    const int cb = (tid & 7) * 8;    // column base   (8 cols)
    const int r0 = (tid >> 3) * 4;   // row base      (4 rows)

    float acc[4][8];
    #pragma unroll
    for (int j = 0; j < 4; j++)
        #pragma unroll
        for (int c = 0; c < 8; c++) acc[j][c] = 0.f;

    #pragma unroll 8
    for (int k = 0; k < K; k++) {
        float4 w0 = *reinterpret_cast<const float4*>(Ws + k * 64 + cb);
        float4 w1 = *reinterpret_cast<const float4*>(Ws + k * 64 + cb + 4);
        #pragma unroll
        for (int j = 0; j < 4; j++) {
            float a = As[(r0 + j) * STR + k];
            acc[j][0] = fmaf(a, w0.x, acc[j][0]);
            acc[j][1] = fmaf(a, w0.y, acc[j][1]);
            acc[j][2] = fmaf(a, w0.z, acc[j][2]);
            acc[j][3] = fmaf(a, w0.w, acc[j][3]);
            acc[j][4] = fmaf(a, w1.x, acc[j][4]);
            acc[j][5] = fmaf(a, w1.y, acc[j][5]);
            acc[j][6] = fmaf(a, w1.z, acc[j][6]);
            acc[j][7] = fmaf(a, w1.w, acc[j][7]);
        }
    }

    const float4 b0 = *reinterpret_cast<const float4*>(bias + cb);
    const float4 b1 = *reinterpret_cast<const float4*>(bias + cb + 4);

    #pragma unroll
    for (int j = 0; j < 4; j++) {
        int gr = row0 + r0 + j;
        if (gr >= N) break;
        float4 v0, v1;
        v0.x = acc[j][0] + b0.x; v0.y = acc[j][1] + b0.y;
        v0.z = acc[j][2] + b0.z; v0.w = acc[j][3] + b0.w;
        v1.x = acc[j][4] + b1.x; v1.y = acc[j][5] + b1.y;
        v1.z = acc[j][6] + b1.z; v1.w = acc[j][7] + b1.w;
        if (RELU) {
            v0.x = fmaxf(v0.x, 0.f); v0.y = fmaxf(v0.y, 0.f);
            v0.z = fmaxf(v0.z, 0.f); v0.w = fmaxf(v0.w, 0.f);
            v1.x = fmaxf(v1.x, 0.f); v1.y = fmaxf(v1.y, 0.f);
            v1.z = fmaxf(v1.z, 0.f); v1.w = fmaxf(v1.w, 0.f);
        }
        float4* op = reinterpret_cast<float4*>(out + (size_t)gr * 64 + cb);
        op[0] = v0;
        op[1] = v1;
    }
}

// ---------------------------------------------------------------------------
// Vector reduction: red.global.add.v4.f32 (sm_90+)
// ---------------------------------------------------------------------------
__device__ __forceinline__ void red_add_v4(float* p, float4 v) {
    asm volatile("red.global.add.v4.f32 [%0], {%1, %2, %3, %4};"
                 :: "l"(p), "f"(v.x), "f"(v.y), "f"(v.z), "f"(v.w)
                 : "memory");
}

// ---------------------------------------------------------------------------
// Edge scatter: agg[dst] += h[src].  Half-warp per edge, float4 per lane.
// ---------------------------------------------------------------------------
__global__ void scatter_kernel(const float* __restrict__ h,
                               const int* __restrict__ ei,
                               float* __restrict__ agg) {
    int warp = blockIdx.x * 8 + (threadIdx.x >> 5);
    int lane = threadIdx.x & 31;
    int e = warp * 2 + (lane >> 4);
    if (e >= NE) return;
    int l16 = lane & 15;
    int s = __ldg(ei + e);        // src
    int d = __ldg(ei + NE + e);   // dst
    if ((unsigned)s >= NN || (unsigned)d >= NN) return;  // defensive
    float4 v = reinterpret_cast<const float4*>(h + (size_t)s * NH)[l16];
    red_add_v4(agg + (size_t)d * NH + l16 * 4, v);
}

// ---------------------------------------------------------------------------
// Global add pool: pool[batch[n]] += h[n].  Half-warp per node.
// ---------------------------------------------------------------------------
__global__ void pool_kernel(const float* __restrict__ h,
                            const int* __restrict__ batch,
                            float* __restrict__ pool) {
    int warp = blockIdx.x * 8 + (threadIdx.x >> 5);
    int lane = threadIdx.x & 31;
    int n = warp * 2 + (lane >> 4);
    if (n >= NN) return;
    int l16 = lane & 15;
    int g = __ldg(batch + n);
    if ((unsigned)g >= NG) return;  // defensive
    float4 v = reinterpret_cast<const float4*>(h + (size_t)n * NH)[l16];
    red_add_v4(pool + (size_t)g * NH + l16 * 4, v);
}

// ---------------------------------------------------------------------------
// Readout: logits = g2 @ roW + rob; out = log_softmax(logits).
// ---------------------------------------------------------------------------
__global__ void readout_kernel(const float* __restrict__ g2,
                               const float* __restrict__ roW,
                               const float* __restrict__ rob,
                               float* __restrict__ out) {
    int row = blockIdx.x * 8 + (threadIdx.x >> 5);
    if (row >= NG) return;
    int lane = threadIdx.x & 31;

    float acc = 0.f;
    if (lane < NC) {
        acc = rob[lane];
        #pragma unroll
        for (int k = 0; k < NH; k++)
            acc = fmaf(g2[(size_t)row * NH + k], roW[k * NC + lane], acc);
    }
    float m = (lane < NC) ? acc : -3.4e38f;
    #pragma unroll
    for (int o = 16; o > 0; o >>= 1)
        m = fmaxf(m, __shfl_xor_sync(0xffffffffu, m, o));
    float e = (lane < NC) ? expf(acc - m) : 0.f;
    float s = e;
    #pragma unroll
    for (int o = 16; o > 0; o >>= 1)
        s += __shfl_xor_sync(0xffffffffu, s, o);
    if (lane < NC) out[(size_t)row * NC + lane] = acc - m - logf(s);
}

// ---------------------------------------------------------------------------
extern "C" void kernel_launch(void* const* d_in, const int* in_sizes, int n_in,
                              void* d_out, int out_size) {
    const float* x      = (const float*)d_in[0];
    const int*   ei     = (const int*)d_in[1];
    const int*   batch  = (const int*)d_in[2];
    const float* pre_w  = (const float*)d_in[3];
    const float* pre_b  = (const float*)d_in[4];
    const float* w1     = (const float*)d_in[5];   // [3,64,64]
    const float* b1     = (const float*)d_in[6];   // [3,64]
    const float* w2     = (const float*)d_in[7];
    const float* b2     = (const float*)d_in[8];
    const float* post_w = (const float*)d_in[9];
    const float* post_b = (const float*)d_in[10];
    const float* ro_w   = (const float*)d_in[11];
    const float* ro_b   = (const float*)d_in[12];
    float*       out    = (float*)d_out;

    float *hP, *aggP, *tP, *poolP, *g2P;
    cudaGetSymbolAddress((void**)&hP,    g_h);
    cudaGetSymbolAddress((void**)&aggP,  g_agg);
    cudaGetSymbolAddress((void**)&tP,    g_t);
    cudaGetSymbolAddress((void**)&poolP, g_pool);
    cudaGetSymbolAddress((void**)&g2P,   g_g2);

    // Dynamic smem sizes
    const int smem_pre = (NF * 64 + 128 * (NF + 1)) * 4;  // 98816 B
    const int smem_hid = (NH * 64 + 128 * (NH + 1)) * 4;  // 49664 B
    cudaFuncSetAttribute(gemm_kernel<NF, false, false>,
                         cudaFuncAttributeMaxDynamicSharedMemorySize, smem_pre);
    cudaFuncSetAttribute(gemm_kernel<NH, true, true>,
                         cudaFuncAttributeMaxDynamicSharedMemorySize, smem_hid);
    cudaFuncSetAttribute(gemm_kernel<NH, true, false>,
                         cudaFuncAttributeMaxDynamicSharedMemorySize, smem_hid);

    // h = x @ pre_w + pre_b
    gemm_kernel<NF, false, false><<<(NN + 127) / 128, 256, smem_pre>>>(
        x, nullptr, pre_w, pre_b, hP, NN);

    for (int l = 0; l < NL; l++) {
        zero_kernel<<<2048, 256>>>(aggP, NN * NH / 4);
        scatter_kernel<<<(NE / 2 + 7) / 8, 256>>>(hP, ei, aggP);
        // t = relu((h + agg) @ w1 + b1)
        gemm_kernel<NH, true, true><<<(NN + 127) / 128, 256, smem_hid>>>(
            hP, aggP, w1 + l * NH * NH, b1 + l * NH, tP, NN);
        // h = relu(t @ w2 + b2)
        gemm_kernel<NH, true, false><<<(NN + 127) / 128, 256, smem_hid>>>(
            tP, nullptr, w2 + l * NH * NH, b2 + l * NH, hP, NN);
    }

    zero_kernel<<<64, 256>>>(poolP, NG * NH / 4);
    pool_kernel<<<(NN / 2 + 7) / 8, 256>>>(hP, batch, poolP);
    // g2 = relu(pool @ post_w + post_b)
    gemm_kernel<NH, true, false><<<(NG + 127) / 128, 256, smem_hid>>>(
        poolP, nullptr, post_w, post_b, g2P, NG);
    readout_kernel<<<(NG + 7) / 8, 256>>>(g2P, ro_w, ro_b, out);
}